// round 9
// baseline (speedup 1.0000x reference)
#include <cuda_runtime.h>
#include <cuda_bf16.h>
#include <cuda_fp16.h>
#include <cstdint>

#define DIMC   256
#define NHEADS 8
#define HDIM   32
#define MAXN   10240   // padded to cover the last 128-row tile

// Scratch (no cudaMalloc allowed).
__device__ __half g_qh[MAXN * DIMC];   // 5.2 MB each
__device__ __half g_kh[MAXN * DIMC];
__device__ __half g_vh[MAXN * DIMC];
__device__ float  g_acc[MAXN * DIMC];  // fp32 accumulator (atomics)

// Pre-split bf16 hi/lo operands in the swizzled smem image.
// Per row: 16 k16-chunks x 4 float4 slots (slot index pre-XORed with row&3).
// Slot s float4 = (hiPair[s], hiPair[s+4], loPair[s], loPair[s+4]).
__device__ float4 gx_s  [MAXN * 64];
__device__ float4 gacc_s[MAXN * 64];
__device__ float4 gw_s  [4 * 256 * 64];

// ---------------------------------------------------------------------------
// bf16 split helpers
// ---------------------------------------------------------------------------
__device__ __forceinline__ void split_pair(float a, float b,
                                           uint32_t& hp, uint32_t& lp)
{
    __nv_bfloat16 ha = __float2bfloat16(a);
    __nv_bfloat16 hb = __float2bfloat16(b);
    float la = a - __bfloat162float(ha);
    float lb = b - __bfloat162float(hb);
    __nv_bfloat16 la16 = __float2bfloat16(la);
    __nv_bfloat16 lb16 = __float2bfloat16(lb);
    hp = (uint32_t)__bfloat16_as_ushort(ha) | ((uint32_t)__bfloat16_as_ushort(hb) << 16);
    lp = (uint32_t)__bfloat16_as_ushort(la16) | ((uint32_t)__bfloat16_as_ushort(lb16) << 16);
}

__device__ __forceinline__ void mma_bf16(float* c,
    uint32_t a0, uint32_t a1, uint32_t a2, uint32_t a3,
    uint32_t b0, uint32_t b1)
{
    asm volatile(
        "mma.sync.aligned.m16n8k16.row.col.f32.bf16.bf16.f32 "
        "{%0,%1,%2,%3}, {%4,%5,%6,%7}, {%8,%9}, {%0,%1,%2,%3};"
        : "+f"(c[0]), "+f"(c[1]), "+f"(c[2]), "+f"(c[3])
        : "r"(a0), "r"(a1), "r"(a2), "r"(a3), "r"(b0), "r"(b1));
}

__device__ __forceinline__ void cpa16(uint32_t dst, const void* src) {
    asm volatile("cp.async.ca.shared.global [%0], [%1], 16;" :: "r"(dst), "l"(src));
}

// ---------------------------------------------------------------------------
// Zero the accumulator.
// ---------------------------------------------------------------------------
__global__ void __launch_bounds__(256) zero_acc_kernel(int n4) {
    int i = blockIdx.x * blockDim.x + threadIdx.x;
    float4 z = make_float4(0.f, 0.f, 0.f, 0.f);
    int stride = gridDim.x * blockDim.x;
    for (; i < n4; i += stride)
        reinterpret_cast<float4*>(g_acc)[i] = z;
}

// ---------------------------------------------------------------------------
// Split kernels (fp32 -> swizzled bf16 hi/lo image).
// ---------------------------------------------------------------------------
__device__ __forceinline__ void split_rowchunk(
    const float* __restrict__ src, float4* __restrict__ dst, int r, int c)
{
    const float4* s = reinterpret_cast<const float4*>(src + (size_t)r * DIMC + c * 16);
    float x[16];
    *reinterpret_cast<float4*>(x + 0)  = s[0];
    *reinterpret_cast<float4*>(x + 4)  = s[1];
    *reinterpret_cast<float4*>(x + 8)  = s[2];
    *reinterpret_cast<float4*>(x + 12) = s[3];
    uint32_t hp[8], lp[8];
#pragma unroll
    for (int t = 0; t < 8; t++) split_pair(x[2 * t], x[2 * t + 1], hp[t], lp[t]);
    float4* d = dst + ((size_t)r * 64 + c * 4);
    int sw = r & 3;
#pragma unroll
    for (int s2 = 0; s2 < 4; s2++)
        d[s2 ^ sw] = make_float4(__uint_as_float(hp[s2]), __uint_as_float(hp[s2 + 4]),
                                 __uint_as_float(lp[s2]), __uint_as_float(lp[s2 + 4]));
}

__global__ void __launch_bounds__(256) split_x_kernel(const float* __restrict__ src, int rows) {
    int idx = blockIdx.x * blockDim.x + threadIdx.x;
    if (idx >= rows * 16) return;
    split_rowchunk(src, gx_s, idx >> 4, idx & 15);
}

__global__ void __launch_bounds__(256) split_acc_kernel(int rows) {
    int idx = blockIdx.x * blockDim.x + threadIdx.x;
    if (idx >= rows * 16) return;
    split_rowchunk(g_acc, gacc_s, idx >> 4, idx & 15);
}

__global__ void __launch_bounds__(256) split_w_kernel(
    const float* __restrict__ Wq, const float* __restrict__ Wk,
    const float* __restrict__ Wv, const float* __restrict__ Wo)
{
    int idx = blockIdx.x * blockDim.x + threadIdx.x;
    if (idx >= 256 * 16) return;
    const float* srcs[4] = {Wq, Wk, Wv, Wo};
    int z = blockIdx.y;
    split_rowchunk(srcs[z], gw_s + (size_t)z * 256 * 64, idx >> 4, idx & 15);
}

// ---------------------------------------------------------------------------
// 3xBF16 tensor-core GEMM (m16n8k16), 4-stage cp.async pipeline.
// OUT_HALF: epilogue converts to fp16 (for q/k/v); else fp32.
// ---------------------------------------------------------------------------
#define BM 128
#define BN 64
#define NCH 16
#define STG 4

template<bool OUT_HALF>
__device__ __forceinline__ void gemm_bf16s(
    const float4* __restrict__ Asrc, int M,
    const float4* __restrict__ Bsrc,
    const float* __restrict__ Bv,
    void* __restrict__ Cv,
    int m0, int n0)
{
    __shared__ float4 As[STG][BM][4];
    __shared__ float4 Bs[STG][BN][4];

    int tid  = threadIdx.x;
    int lane = tid & 31;
    int wid  = tid >> 5;
    int wm = (wid & 3) * 32;
    int wn = (wid >> 2) * 32;
    int gq = lane >> 2;
    int tq = lane & 3;

    int arow = tid >> 1, ahalf = tid & 1;
    const float4* ap = Asrc + (size_t)(m0 + arow) * 64 + ahalf * 2;
    int brow = tid >> 2, bslot = tid & 3;
    const float4* bp = Bsrc + (size_t)(n0 + brow) * 64 + bslot;

    uint32_t sA = (uint32_t)__cvta_generic_to_shared(&As[0][0][0]);
    uint32_t sB = (uint32_t)__cvta_generic_to_shared(&Bs[0][0][0]);
    uint32_t daBase = sA + (uint32_t)((arow * 4 + ahalf * 2) * 16);
    uint32_t dbBase = sB + (uint32_t)((brow * 4 + bslot) * 16);

    float acc[2][4][4];
#pragma unroll
    for (int mi = 0; mi < 2; mi++)
#pragma unroll
        for (int ni = 0; ni < 4; ni++)
#pragma unroll
            for (int j = 0; j < 4; j++) acc[mi][ni][j] = 0.f;

#pragma unroll
    for (int s = 0; s < STG - 1; s++) {
        uint32_t da = daBase + s * (BM * 64);
        uint32_t db = dbBase + s * (BN * 64);
        cpa16(da,      ap + s * 4);
        cpa16(da + 16, ap + s * 4 + 1);
        cpa16(db,      bp + s * 4);
        asm volatile("cp.async.commit_group;");
    }

#pragma unroll 1
    for (int ch = 0; ch < NCH; ch++) {
        asm volatile("cp.async.wait_group %0;" :: "n"(STG - 2) : "memory");
        __syncthreads();
        int st = ch & (STG - 1);

        float4 af0[2], af1[2], bfv[4];
#pragma unroll
        for (int mi = 0; mi < 2; mi++) {
            int r0 = wm + mi * 16 + gq;
            af0[mi] = As[st][r0][tq ^ (r0 & 3)];
            af1[mi] = As[st][r0 + 8][tq ^ (r0 & 3)];
        }
#pragma unroll
        for (int ni = 0; ni < 4; ni++) {
            int rn = wn + ni * 8 + gq;
            bfv[ni] = Bs[st][rn][tq ^ (rn & 3)];
        }

#pragma unroll
        for (int mi = 0; mi < 2; mi++) {
            uint32_t a0h = __float_as_uint(af0[mi].x);
            uint32_t a1h = __float_as_uint(af1[mi].x);
            uint32_t a2h = __float_as_uint(af0[mi].y);
            uint32_t a3h = __float_as_uint(af1[mi].y);
            uint32_t a0l = __float_as_uint(af0[mi].z);
            uint32_t a1l = __float_as_uint(af1[mi].z);
            uint32_t a2l = __float_as_uint(af0[mi].w);
            uint32_t a3l = __float_as_uint(af1[mi].w);
#pragma unroll
            for (int ni = 0; ni < 4; ni++) {
                uint32_t b0h = __float_as_uint(bfv[ni].x);
                uint32_t b1h = __float_as_uint(bfv[ni].y);
                uint32_t b0l = __float_as_uint(bfv[ni].z);
                uint32_t b1l = __float_as_uint(bfv[ni].w);
                mma_bf16(acc[mi][ni], a0h, a1h, a2h, a3h, b0h, b1h);
                mma_bf16(acc[mi][ni], a0h, a1h, a2h, a3h, b0l, b1l);
                mma_bf16(acc[mi][ni], a0l, a1l, a2l, a3l, b0h, b1h);
            }
        }

        int nc = ch + STG - 1;
        if (nc < NCH) {
            int ns = nc & (STG - 1);
            uint32_t da = daBase + ns * (BM * 64);
            uint32_t db = dbBase + ns * (BN * 64);
            cpa16(da,      ap + nc * 4);
            cpa16(da + 16, ap + nc * 4 + 1);
            cpa16(db,      bp + nc * 4);
        }
        asm volatile("cp.async.commit_group;");
    }

    // ---- epilogue: bias + store ----
#pragma unroll
    for (int mi = 0; mi < 2; mi++) {
#pragma unroll
        for (int ni = 0; ni < 4; ni++) {
            int r0 = m0 + wm + mi * 16 + gq;
            int cc = n0 + wn + ni * 8 + 2 * tq;
            float2 bb = *reinterpret_cast<const float2*>(Bv + cc);
            float2 o0 = make_float2(acc[mi][ni][0] + bb.x, acc[mi][ni][1] + bb.y);
            float2 o1 = make_float2(acc[mi][ni][2] + bb.x, acc[mi][ni][3] + bb.y);
            if (OUT_HALF) {
                __half* C = (__half*)Cv;
                if (r0 < M)
                    *reinterpret_cast<__half2*>(C + (size_t)r0 * DIMC + cc) =
                        __floats2half2_rn(o0.x, o0.y);
                if (r0 + 8 < M)
                    *reinterpret_cast<__half2*>(C + (size_t)(r0 + 8) * DIMC + cc) =
                        __floats2half2_rn(o1.x, o1.y);
            } else {
                float* C = (float*)Cv;
                if (r0 < M)
                    *reinterpret_cast<float2*>(C + (size_t)r0 * DIMC + cc) = o0;
                if (r0 + 8 < M)
                    *reinterpret_cast<float2*>(C + (size_t)(r0 + 8) * DIMC + cc) = o1;
            }
        }
    }
}

__global__ void __launch_bounds__(256, 2) gemm_qkv_kernel(
    int M,
    const float* __restrict__ bq, const float* __restrict__ bk,
    const float* __restrict__ bv)
{
    int z = blockIdx.z;
    const float* B = (z == 0) ? bq : (z == 1) ? bk : bv;
    __half* C = (z == 0) ? g_qh : (z == 1) ? g_kh : g_vh;
    gemm_bf16s<true>(gx_s, M, gw_s + (size_t)z * 256 * 64, B, C,
                     blockIdx.y * BM, blockIdx.x * BN);
}

__global__ void __launch_bounds__(256, 2) gemm_out_kernel(
    int M, const float* __restrict__ bo, float* __restrict__ out)
{
    gemm_bf16s<false>(gacc_s, M, gw_s + (size_t)3 * 256 * 64, bo, out,
                      blockIdx.y * BM, blockIdx.x * BN);
}

// ---------------------------------------------------------------------------
// Edge kernel: one warp per edge, fp16 rows (512B).
// Lane l owns elements [8l, 8l+8) -> head l>>2 (4 lanes per head).
// ---------------------------------------------------------------------------
__device__ __forceinline__ void red_add_v4(float* addr, float4 v) {
    asm volatile("red.global.add.v4.f32 [%0], {%1, %2, %3, %4};"
                 :: "l"(addr), "f"(v.x), "f"(v.y), "f"(v.z), "f"(v.w)
                 : "memory");
}

__device__ __forceinline__ void h8_to_f(const float4& raw, float* f) {
    const __half2* h = reinterpret_cast<const __half2*>(&raw);
#pragma unroll
    for (int i = 0; i < 4; i++) {
        float2 t = __half22float2(h[i]);
        f[2 * i] = t.x; f[2 * i + 1] = t.y;
    }
}

__global__ void __launch_bounds__(256) edge_kernel(
    const int* __restrict__ src, const int* __restrict__ dst, int E)
{
    int e = (blockIdx.x << 3) + (threadIdx.x >> 5);
    if (e >= E) return;
    int lane = threadIdx.x & 31;

    int s = src[e];
    int d = dst[e];

    float4 qraw = reinterpret_cast<const float4*>(g_qh + (size_t)s * DIMC)[lane];
    float4 kraw = reinterpret_cast<const float4*>(g_kh + (size_t)d * DIMC)[lane];
    float qf[8], kf[8];
    h8_to_f(qraw, qf);
    h8_to_f(kraw, kf);

    float p = 0.f;
#pragma unroll
    for (int i = 0; i < 8; i++) p = fmaf(qf[i], kf[i], p);

    // Reduce within each aligned 4-lane head group.
    p += __shfl_xor_sync(0xffffffffu, p, 1);
    p += __shfl_xor_sync(0xffffffffu, p, 2);

    const float scale = 0.17677669529663687f;   // 1/sqrt(32)
    float sc = p * scale;                        // score for head lane>>2

    float sh[8];
#pragma unroll
    for (int h = 0; h < 8; h++)
        sh[h] = __shfl_sync(0xffffffffu, sc, h << 2);

    float mx = sh[0];
#pragma unroll
    for (int h = 1; h < 8; h++) mx = fmaxf(mx, sh[h]);
    float sum = 0.f;
#pragma unroll
    for (int h = 0; h < 8; h++) sum += expf(sh[h] - mx);
    float w = expf(sc - mx) / sum;               // attn weight for head lane>>2

    float4 vraw = reinterpret_cast<const float4*>(g_vh + (size_t)s * DIMC)[lane];
    float vf[8];
    h8_to_f(vraw, vf);

    float* op = g_acc + (size_t)d * DIMC + (lane << 3);
    red_add_v4(op,     make_float4(vf[0] * w, vf[1] * w, vf[2] * w, vf[3] * w));
    red_add_v4(op + 4, make_float4(vf[4] * w, vf[5] * w, vf[6] * w, vf[7] * w));
}

// ---------------------------------------------------------------------------
// Launch
// ---------------------------------------------------------------------------
extern "C" void kernel_launch(void* const* d_in, const int* in_sizes, int n_in,
                              void* d_out, int out_size)
{
    const float* x   = (const float*)d_in[0];
    const int*   src = (const int*)  d_in[1];
    const int*   dst = (const int*)  d_in[2];
    const float* Wq  = (const float*)d_in[3];
    const float* bq  = (const float*)d_in[4];
    const float* Wk  = (const float*)d_in[5];
    const float* bk  = (const float*)d_in[6];
    const float* Wv  = (const float*)d_in[7];
    const float* bv  = (const float*)d_in[8];
    const float* Wo  = (const float*)d_in[9];
    const float* bo  = (const float*)d_in[10];
    float* out = (float*)d_out;

    int N = in_sizes[0] / DIMC;
    int E = in_sizes[1];

    int mtiles = (N + BM - 1) / BM;
    int ntiles = DIMC / BN;

    // 1) zero accumulator + split inputs
    int n4 = (N * DIMC) / 4;
    zero_acc_kernel<<<(n4 + 255) / 256, 256>>>(n4);
    split_x_kernel<<<(N * 16 + 255) / 256, 256>>>(x, N);
    {
        dim3 grid((256 * 16 + 255) / 256, 4);
        split_w_kernel<<<grid, 256>>>(Wq, Wk, Wv, Wo);
    }

    // 2) Q/K/V projections (bf16 3-term split, fp16 outputs)
    {
        dim3 grid(ntiles, mtiles, 3);
        gemm_qkv_kernel<<<grid, 256>>>(N, bq, bk, bv);
    }

    // 3) per-edge attention + scatter (fp16 gathers, fp32 reductions)
    edge_kernel<<<(E + 7) / 8, 256>>>(src, dst, E);

    // 4) split aggregated features, output projection (fp32 out)
    split_acc_kernel<<<(N * 16 + 255) / 256, 256>>>(N);
    {
        dim3 grid(ntiles, mtiles, 1);
        gemm_out_kernel<<<grid, 256>>>(N, bo, out);
    }
}

// round 10
// speedup vs baseline: 1.0064x; 1.0064x over previous
#include <cuda_runtime.h>
#include <cuda_bf16.h>
#include <cstdint>

#define DIMC   256
#define NHEADS 8
#define HDIM   32
#define MAXN   10240   // padded to cover the last 128-row tile

// Scratch (no cudaMalloc allowed).
__device__ float g_q[MAXN * DIMC];
__device__ float g_k[MAXN * DIMC];
__device__ float g_v[MAXN * DIMC];
__device__ float g_acc[MAXN * DIMC];

// Pre-split bf16 hi/lo operands in the swizzled smem image.
// Per row: 16 k16-chunks x 4 float4 slots (slot index pre-XORed with row&3).
// Slot s float4 = (hiPair[s], hiPair[s+4], loPair[s], loPair[s+4]).
__device__ float4 gx_s  [MAXN * 64];
__device__ float4 gacc_s[MAXN * 64];
__device__ float4 gw_s  [4 * 256 * 64];

// ---------------------------------------------------------------------------
// bf16 split helpers
// ---------------------------------------------------------------------------
__device__ __forceinline__ void split_pair(float a, float b,
                                           uint32_t& hp, uint32_t& lp)
{
    __nv_bfloat16 ha = __float2bfloat16(a);
    __nv_bfloat16 hb = __float2bfloat16(b);
    float la = a - __bfloat162float(ha);
    float lb = b - __bfloat162float(hb);
    __nv_bfloat16 la16 = __float2bfloat16(la);
    __nv_bfloat16 lb16 = __float2bfloat16(lb);
    hp = (uint32_t)__bfloat16_as_ushort(ha) | ((uint32_t)__bfloat16_as_ushort(hb) << 16);
    lp = (uint32_t)__bfloat16_as_ushort(la16) | ((uint32_t)__bfloat16_as_ushort(lb16) << 16);
}

__device__ __forceinline__ void mma_bf16(float* c,
    uint32_t a0, uint32_t a1, uint32_t a2, uint32_t a3,
    uint32_t b0, uint32_t b1)
{
    asm volatile(
        "mma.sync.aligned.m16n8k16.row.col.f32.bf16.bf16.f32 "
        "{%0,%1,%2,%3}, {%4,%5,%6,%7}, {%8,%9}, {%0,%1,%2,%3};"
        : "+f"(c[0]), "+f"(c[1]), "+f"(c[2]), "+f"(c[3])
        : "r"(a0), "r"(a1), "r"(a2), "r"(a3), "r"(b0), "r"(b1));
}

__device__ __forceinline__ void cpa16(uint32_t dst, const void* src) {
    asm volatile("cp.async.ca.shared.global [%0], [%1], 16;" :: "r"(dst), "l"(src));
}

// ---------------------------------------------------------------------------
// Split helper (fp32 row-chunk -> swizzled bf16 hi/lo image).
// ---------------------------------------------------------------------------
__device__ __forceinline__ void split_rowchunk(
    const float* __restrict__ src, float4* __restrict__ dst, int r, int c)
{
    const float4* s = reinterpret_cast<const float4*>(src + (size_t)r * DIMC + c * 16);
    float x[16];
    *reinterpret_cast<float4*>(x + 0)  = s[0];
    *reinterpret_cast<float4*>(x + 4)  = s[1];
    *reinterpret_cast<float4*>(x + 8)  = s[2];
    *reinterpret_cast<float4*>(x + 12) = s[3];
    uint32_t hp[8], lp[8];
#pragma unroll
    for (int t = 0; t < 8; t++) split_pair(x[2 * t], x[2 * t + 1], hp[t], lp[t]);
    float4* d = dst + ((size_t)r * 64 + c * 4);
    int sw = r & 3;
#pragma unroll
    for (int s2 = 0; s2 < 4; s2++)
        d[s2 ^ sw] = make_float4(__uint_as_float(hp[s2]), __uint_as_float(hp[s2 + 4]),
                                 __uint_as_float(lp[s2]), __uint_as_float(lp[s2 + 4]));
}

// ---------------------------------------------------------------------------
// Prep kernel: one launch does zero(g_acc) + split(x) + split(W*).
// blockIdx ranges select the job.
// ---------------------------------------------------------------------------
__global__ void __launch_bounds__(256) prep_kernel(
    const float* __restrict__ x,
    const float* __restrict__ Wq, const float* __restrict__ Wk,
    const float* __restrict__ Wv, const float* __restrict__ Wo,
    int N, int zeroBlocks, int splitXBlocks)
{
    int b = blockIdx.x;
    if (b < zeroBlocks) {
        int i = b * 256 + threadIdx.x;
        int n4 = N * (DIMC / 4);
        if (i < n4)
            reinterpret_cast<float4*>(g_acc)[i] =
                make_float4(0.f, 0.f, 0.f, 0.f);
    } else if (b < zeroBlocks + splitXBlocks) {
        int idx = (b - zeroBlocks) * 256 + threadIdx.x;
        if (idx < N * 16) split_rowchunk(x, gx_s, idx >> 4, idx & 15);
    } else {
        int idx = (b - zeroBlocks - splitXBlocks) * 256 + threadIdx.x;
        if (idx < 4 * 256 * 16) {
            int z = idx >> 12;              // 4096 chunks per matrix
            int rcl = idx & 4095;
            const float* srcs[4] = {Wq, Wk, Wv, Wo};
            split_rowchunk(srcs[z], gw_s + (size_t)z * 256 * 64, rcl >> 4, rcl & 15);
        }
    }
}

__global__ void __launch_bounds__(256) split_acc_kernel(int rows) {
    int idx = blockIdx.x * blockDim.x + threadIdx.x;
    if (idx >= rows * 16) return;
    split_rowchunk(g_acc, gacc_s, idx >> 4, idx & 15);
}

// ---------------------------------------------------------------------------
// 3xBF16 tensor-core GEMM (m16n8k16), 4-stage cp.async pipeline.
// Re-entrant: safe to call multiple times in sequence from one CTA.
// ---------------------------------------------------------------------------
#define BM 128
#define BN 64
#define NCH 16
#define STG 4

__device__ __forceinline__ void gemm_bf16s(
    const float4* __restrict__ Asrc, int M,
    const float4* __restrict__ Bsrc,
    const float* __restrict__ Bv,
    float* __restrict__ C,
    int m0, int n0,
    float4 (*As)[BM][4], float4 (*Bs)[BN][4])
{
    int tid  = threadIdx.x;
    int lane = tid & 31;
    int wid  = tid >> 5;
    int wm = (wid & 3) * 32;
    int wn = (wid >> 2) * 32;
    int gq = lane >> 2;
    int tq = lane & 3;

    int arow = tid >> 1, ahalf = tid & 1;
    const float4* ap = Asrc + (size_t)(m0 + arow) * 64 + ahalf * 2;
    int brow = tid >> 2, bslot = tid & 3;
    const float4* bp = Bsrc + (size_t)(n0 + brow) * 64 + bslot;

    uint32_t sA = (uint32_t)__cvta_generic_to_shared(&As[0][0][0]);
    uint32_t sB = (uint32_t)__cvta_generic_to_shared(&Bs[0][0][0]);
    uint32_t daBase = sA + (uint32_t)((arow * 4 + ahalf * 2) * 16);
    uint32_t dbBase = sB + (uint32_t)((brow * 4 + bslot) * 16);

    float acc[2][4][4];
#pragma unroll
    for (int mi = 0; mi < 2; mi++)
#pragma unroll
        for (int ni = 0; ni < 4; ni++)
#pragma unroll
            for (int j = 0; j < 4; j++) acc[mi][ni][j] = 0.f;

#pragma unroll
    for (int s = 0; s < STG - 1; s++) {
        uint32_t da = daBase + s * (BM * 64);
        uint32_t db = dbBase + s * (BN * 64);
        cpa16(da,      ap + s * 4);
        cpa16(da + 16, ap + s * 4 + 1);
        cpa16(db,      bp + s * 4);
        asm volatile("cp.async.commit_group;");
    }

#pragma unroll 1
    for (int ch = 0; ch < NCH; ch++) {
        asm volatile("cp.async.wait_group %0;" :: "n"(STG - 2) : "memory");
        __syncthreads();
        int st = ch & (STG - 1);

        float4 af0[2], af1[2], bfv[4];
#pragma unroll
        for (int mi = 0; mi < 2; mi++) {
            int r0 = wm + mi * 16 + gq;
            af0[mi] = As[st][r0][tq ^ (r0 & 3)];
            af1[mi] = As[st][r0 + 8][tq ^ (r0 & 3)];
        }
#pragma unroll
        for (int ni = 0; ni < 4; ni++) {
            int rn = wn + ni * 8 + gq;
            bfv[ni] = Bs[st][rn][tq ^ (rn & 3)];
        }

#pragma unroll
        for (int mi = 0; mi < 2; mi++) {
            uint32_t a0h = __float_as_uint(af0[mi].x);
            uint32_t a1h = __float_as_uint(af1[mi].x);
            uint32_t a2h = __float_as_uint(af0[mi].y);
            uint32_t a3h = __float_as_uint(af1[mi].y);
            uint32_t a0l = __float_as_uint(af0[mi].z);
            uint32_t a1l = __float_as_uint(af1[mi].z);
            uint32_t a2l = __float_as_uint(af0[mi].w);
            uint32_t a3l = __float_as_uint(af1[mi].w);
#pragma unroll
            for (int ni = 0; ni < 4; ni++) {
                uint32_t b0h = __float_as_uint(bfv[ni].x);
                uint32_t b1h = __float_as_uint(bfv[ni].y);
                uint32_t b0l = __float_as_uint(bfv[ni].z);
                uint32_t b1l = __float_as_uint(bfv[ni].w);
                mma_bf16(acc[mi][ni], a0h, a1h, a2h, a3h, b0h, b1h);
                mma_bf16(acc[mi][ni], a0h, a1h, a2h, a3h, b0l, b1l);
                mma_bf16(acc[mi][ni], a0l, a1l, a2l, a3l, b0h, b1h);
            }
        }

        int nc = ch + STG - 1;
        if (nc < NCH) {
            int ns = nc & (STG - 1);
            uint32_t da = daBase + ns * (BM * 64);
            uint32_t db = dbBase + ns * (BN * 64);
            cpa16(da,      ap + nc * 4);
            cpa16(da + 16, ap + nc * 4 + 1);
            cpa16(db,      bp + nc * 4);
        }
        asm volatile("cp.async.commit_group;");
    }

    // ---- epilogue: bias + store ----
#pragma unroll
    for (int mi = 0; mi < 2; mi++) {
#pragma unroll
        for (int ni = 0; ni < 4; ni++) {
            int r0 = m0 + wm + mi * 16 + gq;
            int cc = n0 + wn + ni * 8 + 2 * tq;
            float2 bb = *reinterpret_cast<const float2*>(Bv + cc);
            if (r0 < M) {
                float2 o = make_float2(acc[mi][ni][0] + bb.x,
                                       acc[mi][ni][1] + bb.y);
                *reinterpret_cast<float2*>(C + (size_t)r0 * DIMC + cc) = o;
            }
            if (r0 + 8 < M) {
                float2 o = make_float2(acc[mi][ni][2] + bb.x,
                                       acc[mi][ni][3] + bb.y);
                *reinterpret_cast<float2*>(C + (size_t)(r0 + 8) * DIMC + cc) = o;
            }
        }
    }
}

// Fused persistent-z QKV: one CTA per (m,n) tile, loops z = 0..2.
// 316 CTAs over 296 slots -> ~3.2 tile-times instead of 4 ceil-waves.
__global__ void __launch_bounds__(256, 2) gemm_qkv_kernel(
    int M,
    const float* __restrict__ bq, const float* __restrict__ bk,
    const float* __restrict__ bv)
{
    __shared__ float4 As[STG][BM][4];
    __shared__ float4 Bs[STG][BN][4];

    int t = blockIdx.x;
    int m0 = (t >> 2) * BM;
    int n0 = (t & 3) * BN;

    const float* biases[3] = {bq, bk, bv};
    float* outs[3] = {g_q, g_k, g_v};
#pragma unroll 1
    for (int z = 0; z < 3; z++) {
        gemm_bf16s(gx_s, M, gw_s + (size_t)z * 256 * 64, biases[z], outs[z],
                   m0, n0, As, Bs);
    }
}

__global__ void __launch_bounds__(256, 2) gemm_out_kernel(
    int M, const float* __restrict__ bo, float* __restrict__ out)
{
    __shared__ float4 As[STG][BM][4];
    __shared__ float4 Bs[STG][BN][4];
    gemm_bf16s(gacc_s, M, gw_s + (size_t)3 * 256 * 64, bo, out,
               blockIdx.y * BM, blockIdx.x * BN, As, Bs);
}

// ---------------------------------------------------------------------------
// Edge kernel: one warp per edge, fp32 rows (round-8 proven version).
// ---------------------------------------------------------------------------
__device__ __forceinline__ void red_add_v4(float* addr, float4 v) {
    asm volatile("red.global.add.v4.f32 [%0], {%1, %2, %3, %4};"
                 :: "l"(addr), "f"(v.x), "f"(v.y), "f"(v.z), "f"(v.w)
                 : "memory");
}

__global__ void __launch_bounds__(256) edge_kernel(
    const int* __restrict__ src, const int* __restrict__ dst, int E)
{
    int e = (blockIdx.x << 3) + (threadIdx.x >> 5);
    if (e >= E) return;
    int lane = threadIdx.x & 31;

    int s = src[e];
    int d = dst[e];

    const float4* qp = reinterpret_cast<const float4*>(g_q + (size_t)s * DIMC);
    const float4* kp = reinterpret_cast<const float4*>(g_k + (size_t)d * DIMC);

    float4 a0 = qp[lane];
    float4 a1 = qp[lane + 32];
    float4 b0 = kp[lane];
    float4 b1 = kp[lane + 32];

    float p0 = a0.x * b0.x + a0.y * b0.y + a0.z * b0.z + a0.w * b0.w;
    float p1 = a1.x * b1.x + a1.y * b1.y + a1.z * b1.z + a1.w * b1.w;

#pragma unroll
    for (int m = 1; m <= 4; m <<= 1) {
        p0 += __shfl_xor_sync(0xffffffffu, p0, m);
        p1 += __shfl_xor_sync(0xffffffffu, p1, m);
    }

    const float scale = 0.17677669529663687f;   // 1/sqrt(32)
    float sc0 = p0 * scale;
    float sc1 = p1 * scale;

    float sh[8];
#pragma unroll
    for (int h = 0; h < 4; h++) {
        sh[h]     = __shfl_sync(0xffffffffu, sc0, h << 3);
        sh[h + 4] = __shfl_sync(0xffffffffu, sc1, h << 3);
    }

    float mx = sh[0];
#pragma unroll
    for (int h = 1; h < 8; h++) mx = fmaxf(mx, sh[h]);
    float sum = 0.f;
#pragma unroll
    for (int h = 0; h < 8; h++) sum += expf(sh[h] - mx);
    float inv = 1.0f / sum;

    float w0 = expf(sc0 - mx) * inv;
    float w1 = expf(sc1 - mx) * inv;

    const float4* vp = reinterpret_cast<const float4*>(g_v + (size_t)s * DIMC);
    float4 v0 = vp[lane];
    float4 v1 = vp[lane + 32];

    float* op = g_acc + (size_t)d * DIMC;
    red_add_v4(op + (lane << 2),
               make_float4(v0.x * w0, v0.y * w0, v0.z * w0, v0.w * w0));
    red_add_v4(op + ((lane + 32) << 2),
               make_float4(v1.x * w1, v1.y * w1, v1.z * w1, v1.w * w1));
}

// ---------------------------------------------------------------------------
// Launch
// ---------------------------------------------------------------------------
extern "C" void kernel_launch(void* const* d_in, const int* in_sizes, int n_in,
                              void* d_out, int out_size)
{
    const float* x   = (const float*)d_in[0];
    const int*   src = (const int*)  d_in[1];
    const int*   dst = (const int*)  d_in[2];
    const float* Wq  = (const float*)d_in[3];
    const float* bq  = (const float*)d_in[4];
    const float* Wk  = (const float*)d_in[5];
    const float* bk  = (const float*)d_in[6];
    const float* Wv  = (const float*)d_in[7];
    const float* bv  = (const float*)d_in[8];
    const float* Wo  = (const float*)d_in[9];
    const float* bo  = (const float*)d_in[10];
    float* out = (float*)d_out;

    int N = in_sizes[0] / DIMC;
    int E = in_sizes[1];

    int mtiles = (N + BM - 1) / BM;
    int ntiles = DIMC / BN;

    // 1) prep: zero g_acc + split x + split W (single launch)
    int zeroBlocks   = (N * (DIMC / 4) + 255) / 256;
    int splitXBlocks = (N * 16 + 255) / 256;
    int splitWBlocks = (4 * 256 * 16 + 255) / 256;
    prep_kernel<<<zeroBlocks + splitXBlocks + splitWBlocks, 256>>>(
        x, Wq, Wk, Wv, Wo, N, zeroBlocks, splitXBlocks);

    // 2) Q/K/V projections (fused persistent-z)
    gemm_qkv_kernel<<<mtiles * ntiles, 256>>>(N, bq, bk, bv);

    // 3) per-edge attention + scatter
    edge_kernel<<<(E + 7) / 8, 256>>>(src, dst, E);

    // 4) split aggregated features, output projection
    split_acc_kernel<<<(N * 16 + 255) / 256, 256>>>(N);
    {
        dim3 grid(ntiles, mtiles, 1);
        gemm_out_kernel<<<grid, 256>>>(N, bo, out);
    }
}

// round 11
// speedup vs baseline: 1.0688x; 1.0620x over previous
#include <cuda_runtime.h>
#include <cuda_bf16.h>
#include <cstdint>

#define DIMC   256
#define NHEADS 8
#define HDIM   32
#define MAXN   10240   // padded: loaders never read past row 10239

// Scratch (no cudaMalloc allowed).
__device__ float g_q[MAXN * DIMC];
__device__ float g_k[MAXN * DIMC];
__device__ float g_v[MAXN * DIMC];
__device__ float g_acc[MAXN * DIMC];

// Pre-split bf16 hi/lo operands in the swizzled smem image.
// Per row: 16 k16-chunks x 4 float4 slots (slot index pre-XORed with row&3).
// Slot s float4 = (hiPair[s], hiPair[s+4], loPair[s], loPair[s+4]).
__device__ float4 gx_s  [MAXN * 64];
__device__ float4 gacc_s[MAXN * 64];
__device__ float4 gw_s  [4 * 256 * 64];

// ---------------------------------------------------------------------------
// bf16 split helpers
// ---------------------------------------------------------------------------
__device__ __forceinline__ void split_pair(float a, float b,
                                           uint32_t& hp, uint32_t& lp)
{
    __nv_bfloat16 ha = __float2bfloat16(a);
    __nv_bfloat16 hb = __float2bfloat16(b);
    float la = a - __bfloat162float(ha);
    float lb = b - __bfloat162float(hb);
    __nv_bfloat16 la16 = __float2bfloat16(la);
    __nv_bfloat16 lb16 = __float2bfloat16(lb);
    hp = (uint32_t)__bfloat16_as_ushort(ha) | ((uint32_t)__bfloat16_as_ushort(hb) << 16);
    lp = (uint32_t)__bfloat16_as_ushort(la16) | ((uint32_t)__bfloat16_as_ushort(lb16) << 16);
}

__device__ __forceinline__ void mma_bf16(float* c,
    uint32_t a0, uint32_t a1, uint32_t a2, uint32_t a3,
    uint32_t b0, uint32_t b1)
{
    asm volatile(
        "mma.sync.aligned.m16n8k16.row.col.f32.bf16.bf16.f32 "
        "{%0,%1,%2,%3}, {%4,%5,%6,%7}, {%8,%9}, {%0,%1,%2,%3};"
        : "+f"(c[0]), "+f"(c[1]), "+f"(c[2]), "+f"(c[3])
        : "r"(a0), "r"(a1), "r"(a2), "r"(a3), "r"(b0), "r"(b1));
}

__device__ __forceinline__ void cpa16(uint32_t dst, const void* src) {
    asm volatile("cp.async.ca.shared.global [%0], [%1], 16;" :: "r"(dst), "l"(src));
}

// ---------------------------------------------------------------------------
// Split helper (fp32 row-chunk -> swizzled bf16 hi/lo image).
// ---------------------------------------------------------------------------
__device__ __forceinline__ void split_rowchunk(
    const float* __restrict__ src, float4* __restrict__ dst, int r, int c)
{
    const float4* s = reinterpret_cast<const float4*>(src + (size_t)r * DIMC + c * 16);
    float x[16];
    *reinterpret_cast<float4*>(x + 0)  = s[0];
    *reinterpret_cast<float4*>(x + 4)  = s[1];
    *reinterpret_cast<float4*>(x + 8)  = s[2];
    *reinterpret_cast<float4*>(x + 12) = s[3];
    uint32_t hp[8], lp[8];
#pragma unroll
    for (int t = 0; t < 8; t++) split_pair(x[2 * t], x[2 * t + 1], hp[t], lp[t]);
    float4* d = dst + ((size_t)r * 64 + c * 4);
    int sw = r & 3;
#pragma unroll
    for (int s2 = 0; s2 < 4; s2++)
        d[s2 ^ sw] = make_float4(__uint_as_float(hp[s2]), __uint_as_float(hp[s2 + 4]),
                                 __uint_as_float(lp[s2]), __uint_as_float(lp[s2 + 4]));
}

// ---------------------------------------------------------------------------
// Prep kernel: one launch does zero(g_acc) + split(x) + split(W*).
// ---------------------------------------------------------------------------
__global__ void __launch_bounds__(256) prep_kernel(
    const float* __restrict__ x,
    const float* __restrict__ Wq, const float* __restrict__ Wk,
    const float* __restrict__ Wv, const float* __restrict__ Wo,
    int N, int zeroBlocks, int splitXBlocks)
{
    int b = blockIdx.x;
    if (b < zeroBlocks) {
        int i = b * 256 + threadIdx.x;
        int n4 = N * (DIMC / 4);
        if (i < n4)
            reinterpret_cast<float4*>(g_acc)[i] = make_float4(0.f, 0.f, 0.f, 0.f);
    } else if (b < zeroBlocks + splitXBlocks) {
        int idx = (b - zeroBlocks) * 256 + threadIdx.x;
        if (idx < N * 16) split_rowchunk(x, gx_s, idx >> 4, idx & 15);
    } else {
        int idx = (b - zeroBlocks - splitXBlocks) * 256 + threadIdx.x;
        if (idx < 4 * 256 * 16) {
            int z = idx >> 12;
            int rcl = idx & 4095;
            const float* srcs[4] = {Wq, Wk, Wv, Wo};
            split_rowchunk(srcs[z], gw_s + (size_t)z * 256 * 64, rcl >> 4, rcl & 15);
        }
    }
}

__global__ void __launch_bounds__(256) split_acc_kernel(int rows) {
    int idx = blockIdx.x * blockDim.x + threadIdx.x;
    if (idx >= rows * 16) return;
    split_rowchunk(g_acc, gacc_s, idx >> 4, idx & 15);
}

// ---------------------------------------------------------------------------
// 3xBF16 tensor-core GEMM (m16n8k16), 4-stage cp.async pipeline.
// CTA tile 64x64, 128 threads (4 warps, 32x32 warp tiles) -> ~5 CTAs/SM.
// ---------------------------------------------------------------------------
#define BM 64
#define BN 64
#define NCH 16
#define STG 4

__device__ __forceinline__ void gemm_bf16s(
    const float4* __restrict__ Asrc, int M,
    const float4* __restrict__ Bsrc,
    const float* __restrict__ Bv,
    float* __restrict__ C,
    int m0, int n0)
{
    __shared__ float4 As[STG][BM][4];   // 16 KB
    __shared__ float4 Bs[STG][BN][4];   // 16 KB

    int tid  = threadIdx.x;
    int lane = tid & 31;
    int wid  = tid >> 5;                // 0..3
    int wm = (wid & 1) * 32;
    int wn = (wid >> 1) * 32;
    int gq = lane >> 2;
    int tq = lane & 3;

    // Loaders: 128 threads; A: (row=tid>>1, half=tid&1) -> 2 f4 (32B).
    //          B: same mapping.
    int lrow = tid >> 1, lhalf = tid & 1;
    const float4* ap = Asrc + (size_t)(m0 + lrow) * 64 + lhalf * 2;
    const float4* bp = Bsrc + (size_t)(n0 + lrow) * 64 + lhalf * 2;

    uint32_t sA = (uint32_t)__cvta_generic_to_shared(&As[0][0][0]);
    uint32_t sB = (uint32_t)__cvta_generic_to_shared(&Bs[0][0][0]);
    uint32_t daBase = sA + (uint32_t)((lrow * 4 + lhalf * 2) * 16);
    uint32_t dbBase = sB + (uint32_t)((lrow * 4 + lhalf * 2) * 16);

    float acc[2][4][4];
#pragma unroll
    for (int mi = 0; mi < 2; mi++)
#pragma unroll
        for (int ni = 0; ni < 4; ni++)
#pragma unroll
            for (int j = 0; j < 4; j++) acc[mi][ni][j] = 0.f;

#pragma unroll
    for (int s = 0; s < STG - 1; s++) {
        uint32_t da = daBase + s * (BM * 64);
        uint32_t db = dbBase + s * (BN * 64);
        cpa16(da,      ap + s * 4);
        cpa16(da + 16, ap + s * 4 + 1);
        cpa16(db,      bp + s * 4);
        cpa16(db + 16, bp + s * 4 + 1);
        asm volatile("cp.async.commit_group;");
    }

#pragma unroll 1
    for (int ch = 0; ch < NCH; ch++) {
        asm volatile("cp.async.wait_group %0;" :: "n"(STG - 2) : "memory");
        __syncthreads();
        int st = ch & (STG - 1);

        float4 af0[2], af1[2], bfv[4];
#pragma unroll
        for (int mi = 0; mi < 2; mi++) {
            int r0 = wm + mi * 16 + gq;
            af0[mi] = As[st][r0][tq ^ (r0 & 3)];
            af1[mi] = As[st][r0 + 8][tq ^ (r0 & 3)];
        }
#pragma unroll
        for (int ni = 0; ni < 4; ni++) {
            int rn = wn + ni * 8 + gq;
            bfv[ni] = Bs[st][rn][tq ^ (rn & 3)];
        }

#pragma unroll
        for (int mi = 0; mi < 2; mi++) {
            uint32_t a0h = __float_as_uint(af0[mi].x);
            uint32_t a1h = __float_as_uint(af1[mi].x);
            uint32_t a2h = __float_as_uint(af0[mi].y);
            uint32_t a3h = __float_as_uint(af1[mi].y);
            uint32_t a0l = __float_as_uint(af0[mi].z);
            uint32_t a1l = __float_as_uint(af1[mi].z);
            uint32_t a2l = __float_as_uint(af0[mi].w);
            uint32_t a3l = __float_as_uint(af1[mi].w);
#pragma unroll
            for (int ni = 0; ni < 4; ni++) {
                uint32_t b0h = __float_as_uint(bfv[ni].x);
                uint32_t b1h = __float_as_uint(bfv[ni].y);
                uint32_t b0l = __float_as_uint(bfv[ni].z);
                uint32_t b1l = __float_as_uint(bfv[ni].w);
                mma_bf16(acc[mi][ni], a0h, a1h, a2h, a3h, b0h, b1h);
                mma_bf16(acc[mi][ni], a0h, a1h, a2h, a3h, b0l, b1l);
                mma_bf16(acc[mi][ni], a0l, a1l, a2l, a3l, b0h, b1h);
            }
        }

        int nc = ch + STG - 1;
        if (nc < NCH) {
            int ns = nc & (STG - 1);
            uint32_t da = daBase + ns * (BM * 64);
            uint32_t db = dbBase + ns * (BN * 64);
            cpa16(da,      ap + nc * 4);
            cpa16(da + 16, ap + nc * 4 + 1);
            cpa16(db,      bp + nc * 4);
            cpa16(db + 16, bp + nc * 4 + 1);
        }
        asm volatile("cp.async.commit_group;");
    }

    // ---- epilogue: bias + store ----
#pragma unroll
    for (int mi = 0; mi < 2; mi++) {
#pragma unroll
        for (int ni = 0; ni < 4; ni++) {
            int r0 = m0 + wm + mi * 16 + gq;
            int cc = n0 + wn + ni * 8 + 2 * tq;
            float2 bb = *reinterpret_cast<const float2*>(Bv + cc);
            if (r0 < M) {
                float2 o = make_float2(acc[mi][ni][0] + bb.x,
                                       acc[mi][ni][1] + bb.y);
                *reinterpret_cast<float2*>(C + (size_t)r0 * DIMC + cc) = o;
            }
            if (r0 + 8 < M) {
                float2 o = make_float2(acc[mi][ni][2] + bb.x,
                                       acc[mi][ni][3] + bb.y);
                *reinterpret_cast<float2*>(C + (size_t)(r0 + 8) * DIMC + cc) = o;
            }
        }
    }
}

__global__ void __launch_bounds__(128, 5) gemm_qkv_kernel(
    int M,
    const float* __restrict__ bq, const float* __restrict__ bk,
    const float* __restrict__ bv)
{
    int z = blockIdx.z;
    const float* B = (z == 0) ? bq : (z == 1) ? bk : bv;
    float* C = (z == 0) ? g_q : (z == 1) ? g_k : g_v;
    gemm_bf16s(gx_s, M, gw_s + (size_t)z * 256 * 64, B, C,
               blockIdx.y * BM, blockIdx.x * BN);
}

__global__ void __launch_bounds__(128, 5) gemm_out_kernel(
    int M, const float* __restrict__ bo, float* __restrict__ out)
{
    gemm_bf16s(gacc_s, M, gw_s + (size_t)3 * 256 * 64, bo, out,
               blockIdx.y * BM, blockIdx.x * BN);
}

// ---------------------------------------------------------------------------
// Edge kernel: one warp per edge, fp32 rows (round-8 proven version).
// ---------------------------------------------------------------------------
__device__ __forceinline__ void red_add_v4(float* addr, float4 v) {
    asm volatile("red.global.add.v4.f32 [%0], {%1, %2, %3, %4};"
                 :: "l"(addr), "f"(v.x), "f"(v.y), "f"(v.z), "f"(v.w)
                 : "memory");
}

__global__ void __launch_bounds__(256) edge_kernel(
    const int* __restrict__ src, const int* __restrict__ dst, int E)
{
    int e = (blockIdx.x << 3) + (threadIdx.x >> 5);
    if (e >= E) return;
    int lane = threadIdx.x & 31;

    int s = src[e];
    int d = dst[e];

    const float4* qp = reinterpret_cast<const float4*>(g_q + (size_t)s * DIMC);
    const float4* kp = reinterpret_cast<const float4*>(g_k + (size_t)d * DIMC);

    float4 a0 = qp[lane];
    float4 a1 = qp[lane + 32];
    float4 b0 = kp[lane];
    float4 b1 = kp[lane + 32];

    float p0 = a0.x * b0.x + a0.y * b0.y + a0.z * b0.z + a0.w * b0.w;
    float p1 = a1.x * b1.x + a1.y * b1.y + a1.z * b1.z + a1.w * b1.w;

#pragma unroll
    for (int m = 1; m <= 4; m <<= 1) {
        p0 += __shfl_xor_sync(0xffffffffu, p0, m);
        p1 += __shfl_xor_sync(0xffffffffu, p1, m);
    }

    const float scale = 0.17677669529663687f;   // 1/sqrt(32)
    float sc0 = p0 * scale;
    float sc1 = p1 * scale;

    float sh[8];
#pragma unroll
    for (int h = 0; h < 4; h++) {
        sh[h]     = __shfl_sync(0xffffffffu, sc0, h << 3);
        sh[h + 4] = __shfl_sync(0xffffffffu, sc1, h << 3);
    }

    float mx = sh[0];
#pragma unroll
    for (int h = 1; h < 8; h++) mx = fmaxf(mx, sh[h]);
    float sum = 0.f;
#pragma unroll
    for (int h = 0; h < 8; h++) sum += expf(sh[h] - mx);
    float inv = 1.0f / sum;

    float w0 = expf(sc0 - mx) * inv;
    float w1 = expf(sc1 - mx) * inv;

    const float4* vp = reinterpret_cast<const float4*>(g_v + (size_t)s * DIMC);
    float4 v0 = vp[lane];
    float4 v1 = vp[lane + 32];

    float* op = g_acc + (size_t)d * DIMC;
    red_add_v4(op + (lane << 2),
               make_float4(v0.x * w0, v0.y * w0, v0.z * w0, v0.w * w0));
    red_add_v4(op + ((lane + 32) << 2),
               make_float4(v1.x * w1, v1.y * w1, v1.z * w1, v1.w * w1));
}

// ---------------------------------------------------------------------------
// Launch
// ---------------------------------------------------------------------------
extern "C" void kernel_launch(void* const* d_in, const int* in_sizes, int n_in,
                              void* d_out, int out_size)
{
    const float* x   = (const float*)d_in[0];
    const int*   src = (const int*)  d_in[1];
    const int*   dst = (const int*)  d_in[2];
    const float* Wq  = (const float*)d_in[3];
    const float* bq  = (const float*)d_in[4];
    const float* Wk  = (const float*)d_in[5];
    const float* bk  = (const float*)d_in[6];
    const float* Wv  = (const float*)d_in[7];
    const float* bv  = (const float*)d_in[8];
    const float* Wo  = (const float*)d_in[9];
    const float* bo  = (const float*)d_in[10];
    float* out = (float*)d_out;

    int N = in_sizes[0] / DIMC;
    int E = in_sizes[1];

    int mtiles = (N + BM - 1) / BM;   // 157
    int ntiles = DIMC / BN;           // 4

    // 1) prep: zero g_acc + split x + split W (single launch)
    int zeroBlocks   = (N * (DIMC / 4) + 255) / 256;
    int splitXBlocks = (N * 16 + 255) / 256;
    int splitWBlocks = (4 * 256 * 16 + 255) / 256;
    prep_kernel<<<zeroBlocks + splitXBlocks + splitWBlocks, 256>>>(
        x, Wq, Wk, Wv, Wo, N, zeroBlocks, splitXBlocks);

    // 2) Q/K/V projections (z-split grid; small CTAs for occupancy)
    {
        dim3 grid(ntiles, mtiles, 3);
        gemm_qkv_kernel<<<grid, 128>>>(N, bq, bk, bv);
    }

    // 3) per-edge attention + scatter
    edge_kernel<<<(E + 7) / 8, 256>>>(src, dst, E);

    // 4) split aggregated features, output projection
    split_acc_kernel<<<(N * 16 + 255) / 256, 256>>>(N);
    {
        dim3 grid(ntiles, mtiles, 1);
        gemm_out_kernel<<<grid, 128>>>(N, bo, out);
    }
}